// round 2
// baseline (speedup 1.0000x reference)
#include <cuda_runtime.h>
#include <stdint.h>

#define CIN   64
#define COUT  64
#define HW    16384     // 128*128
#define NB    32
#define NGRP  16        // channel groups of 4

// prep outputs (device scratch; no allocation)
__device__ int   g_wpack[NGRP * COUT];   // [group][o] packed s8 weights
__device__ float g_S[COUT];
__device__ float g_C0[COUT];
__device__ float g_C1[COUT];

__global__ void prep_kernel(const int* __restrict__ w,
                            const float* __restrict__ wscale,
                            const int* __restrict__ wzp,
                            const float* __restrict__ bias,
                            const float* __restrict__ iscale,
                            const float* __restrict__ oscale,
                            const int* __restrict__ izp_p) {
    int o = threadIdx.x;
    if (o >= COUT) return;
    int sum = 0;
#pragma unroll
    for (int g = 0; g < NGRP; g++) {
        unsigned word = 0;
#pragma unroll
        for (int j = 0; j < 4; j++) {
            int v = w[o * CIN + g * 4 + j];
            sum += v;
            word |= (unsigned)(v & 0xFF) << (8 * j);
        }
        g_wpack[g * COUT + o] = (int)word;
    }
    float s   = iscale[0] * wscale[o] / oscale[0];
    float izp = (float)izp_p[0];
    float zw  = (float)wzp[o];
    g_S[o]  = s;
    g_C1[o] = -s * zw;
    g_C0[o] = bias[o] / oscale[0] + s * izp * (64.0f * zw - (float)sum);
}

__device__ __forceinline__ int dp4a_us(unsigned a, int b, int c) {
    int r;
    asm("dp4a.u32.s32 %0, %1, %2, %3;" : "=r"(r) : "r"(a), "r"(b), "r"(c));
    return r;
}

__device__ __forceinline__ unsigned pack4(int a, int b, int c, int d) {
    unsigned lo = __byte_perm((unsigned)a, (unsigned)b, 0x0040);
    unsigned hi = __byte_perm((unsigned)c, (unsigned)d, 0x0040);
    return __byte_perm(lo, hi, 0x5410);
}

__global__ __launch_bounds__(256) void conv_kernel(const int4* __restrict__ x,
                                                   float4* __restrict__ out,
                                                   const int* __restrict__ ozp_p) {
    __shared__ int   s_w[NGRP * COUT];
    __shared__ float s_S[COUT], s_C0[COUT], s_C1[COUT];
    int tid = threadIdx.x;
    for (int i = tid; i < NGRP * COUT; i += 256) s_w[i] = g_wpack[i];
    if (tid < COUT) {
        s_S[tid]  = g_S[tid];
        s_C0[tid] = g_C0[tid];
        s_C1[tid] = g_C1[tid];
    }
    __syncthreads();

    const float ozp = (float)ozp_p[0];
    int gp4 = blockIdx.x * 256 + tid;     // one group = 4 consecutive w positions
    int gp  = gp4 << 2;
    int b   = gp >> 14;                    // / HW
    int hw  = gp & (HW - 1);

    const int4* xb = x + (b * (CIN * HW / 4) + (hw >> 2));

    // load 64 channels x 4 positions; pack to u8x4 words per (group, position)
    unsigned xw[NGRP][4];
#pragma unroll
    for (int g = 0; g < NGRP; g++) {
        int4 a0 = __ldg(xb + (g * 4 + 0) * (HW / 4));
        int4 a1 = __ldg(xb + (g * 4 + 1) * (HW / 4));
        int4 a2 = __ldg(xb + (g * 4 + 2) * (HW / 4));
        int4 a3 = __ldg(xb + (g * 4 + 3) * (HW / 4));
        xw[g][0] = pack4(a0.x, a1.x, a2.x, a3.x);
        xw[g][1] = pack4(a0.y, a1.y, a2.y, a3.y);
        xw[g][2] = pack4(a0.z, a1.z, a2.z, a3.z);
        xw[g][3] = pack4(a0.w, a1.w, a2.w, a3.w);
    }

    // per-position channel sums (for weight zero-point term)
    int sx[4] = {0, 0, 0, 0};
#pragma unroll
    for (int g = 0; g < NGRP; g++) {
#pragma unroll
        for (int p = 0; p < 4; p++)
            sx[p] = dp4a_us(xw[g][p], 0x01010101, sx[p]);
    }
    float sxf[4];
#pragma unroll
    for (int p = 0; p < 4; p++) sxf[p] = (float)sx[p];

    const int out_base = b * COUT * (HW / 4) + (hw >> 2);   // in float4 units

    for (int q = 0; q < NGRP; q++) {      // 16 output-channel quads
        int acc[4][4] = {};               // [out-in-quad][position]
#pragma unroll
        for (int g = 0; g < NGRP; g++) {
            int4 w4 = *(const int4*)(s_w + g * COUT + q * 4);
#pragma unroll
            for (int p = 0; p < 4; p++) {
                acc[0][p] = dp4a_us(xw[g][p], w4.x, acc[0][p]);
                acc[1][p] = dp4a_us(xw[g][p], w4.y, acc[1][p]);
                acc[2][p] = dp4a_us(xw[g][p], w4.z, acc[2][p]);
                acc[3][p] = dp4a_us(xw[g][p], w4.w, acc[3][p]);
            }
        }
#pragma unroll
        for (int j = 0; j < 4; j++) {
            int o = q * 4 + j;
            float S  = s_S[o];
            float C0 = s_C0[o];
            float C1 = s_C1[o];
            float r[4];
#pragma unroll
            for (int p = 0; p < 4; p++) {
                float f = fmaf(S, (float)acc[j][p], fmaf(C1, sxf[p], C0));
                float v = (float)__float2int_rn(f) + ozp;
                r[p] = fminf(fmaxf(v, 0.0f), 255.0f);
            }
            out[out_base + o * (HW / 4)] = make_float4(r[0], r[1], r[2], r[3]);
        }
    }
}

extern "C" void kernel_launch(void* const* d_in, const int* in_sizes, int n_in,
                              void* d_out, int out_size) {
    // metadata order:
    // 0: x_quant (int32)       1: input_scale (f32)   2: input_zero_point (i32)
    // 3: weight_int8 (i32)     4: weight_scale (f32)  5: weight_zero_point (i32)
    // 6: bias_fp32 (f32)       7: output_scale (f32)  8: output_zero_point (i32)
    (void)in_sizes; (void)n_in; (void)out_size;

    prep_kernel<<<1, 64>>>((const int*)d_in[3], (const float*)d_in[4],
                           (const int*)d_in[5], (const float*)d_in[6],
                           (const float*)d_in[1], (const float*)d_in[7],
                           (const int*)d_in[2]);

    // 524288 positions / 4 per thread / 256 threads = 512 blocks (exact)
    conv_kernel<<<512, 256>>>((const int4*)d_in[0], (float4*)d_out,
                              (const int*)d_in[8]);
}

// round 3
// speedup vs baseline: 1.2460x; 1.2460x over previous
#include <cuda_runtime.h>
#include <stdint.h>

#define CIN   64
#define COUT  64
#define HW    16384     // 128*128
#define NGRP  16        // input-channel groups of 4

// prep outputs (device scratch; no allocation)
__device__ int   g_wpack[NGRP * COUT];   // [group][o] packed s8 weights
__device__ float g_S[COUT];
__device__ float g_C0[COUT];             // includes bias/os + izp term + ozp
__device__ float g_C1[COUT];

__global__ void prep_kernel(const int* __restrict__ w,
                            const float* __restrict__ wscale,
                            const int* __restrict__ wzp,
                            const float* __restrict__ bias,
                            const float* __restrict__ iscale,
                            const float* __restrict__ oscale,
                            const int* __restrict__ izp_p,
                            const int* __restrict__ ozp_p) {
    int o = threadIdx.x;
    if (o >= COUT) return;
    int sum = 0;
#pragma unroll
    for (int g = 0; g < NGRP; g++) {
        unsigned word = 0;
#pragma unroll
        for (int j = 0; j < 4; j++) {
            int v = w[o * CIN + g * 4 + j];
            sum += v;
            word |= (unsigned)(v & 0xFF) << (8 * j);
        }
        g_wpack[g * COUT + o] = (int)word;
    }
    float s   = iscale[0] * wscale[o] / oscale[0];
    float izp = (float)izp_p[0];
    float zw  = (float)wzp[o];
    g_S[o]  = s;
    g_C1[o] = -s * zw;
    // round(f) + ozp == round(f + ozp) for integer ozp -> fold ozp here
    g_C0[o] = bias[o] / oscale[0] + s * izp * (64.0f * zw - (float)sum)
            + (float)ozp_p[0];
}

__device__ __forceinline__ int dp4a_us(unsigned a, int b, int c) {
    int r;
    asm("dp4a.u32.s32 %0, %1, %2, %3;" : "=r"(r) : "r"(a), "r"(b), "r"(c));
    return r;
}

__device__ __forceinline__ unsigned pack4(int a, int b, int c, int d) {
    unsigned lo = __byte_perm((unsigned)a, (unsigned)b, 0x0040);
    unsigned hi = __byte_perm((unsigned)c, (unsigned)d, 0x0040);
    return __byte_perm(lo, hi, 0x5410);
}

__global__ __launch_bounds__(256, 3) void conv_kernel(const int2* __restrict__ x,
                                                      float2* __restrict__ out) {
    __shared__ int   s_w[NGRP * COUT];
    __shared__ float s_S[COUT], s_C0[COUT], s_C1[COUT];
    int tid = threadIdx.x;
    for (int i = tid; i < NGRP * COUT; i += 256) s_w[i] = g_wpack[i];
    if (tid < COUT) {
        s_S[tid]  = g_S[tid];
        s_C0[tid] = g_C0[tid];
        s_C1[tid] = g_C1[tid];
    }
    __syncthreads();

    int gp2 = blockIdx.x * 256 + tid;     // one group = 2 consecutive w positions
    int gp  = gp2 << 1;
    int b   = gp >> 14;                    // / HW
    int hw  = gp & (HW - 1);

    const int2* xb = x + (b * (CIN * HW / 2) + (hw >> 1));

    // load 64 channels x 2 positions; pack to u8x4 words per (group, position)
    unsigned xw[NGRP][2];
#pragma unroll
    for (int g = 0; g < NGRP; g++) {
        int2 a0 = __ldg(xb + (g * 4 + 0) * (HW / 2));
        int2 a1 = __ldg(xb + (g * 4 + 1) * (HW / 2));
        int2 a2 = __ldg(xb + (g * 4 + 2) * (HW / 2));
        int2 a3 = __ldg(xb + (g * 4 + 3) * (HW / 2));
        xw[g][0] = pack4(a0.x, a1.x, a2.x, a3.x);
        xw[g][1] = pack4(a0.y, a1.y, a2.y, a3.y);
    }

    // per-position channel sums (for weight zero-point term)
    int sx0 = 0, sx1 = 0;
#pragma unroll
    for (int g = 0; g < NGRP; g++) {
        sx0 = dp4a_us(xw[g][0], 0x01010101, sx0);
        sx1 = dp4a_us(xw[g][1], 0x01010101, sx1);
    }
    float sxf0 = (float)sx0, sxf1 = (float)sx1;

    const int out_base = b * COUT * (HW / 2) + (hw >> 1);   // in float2 units

    for (int q = 0; q < NGRP; q++) {      // 16 output-channel quads
        int acc[4][2] = {};               // [out-in-quad][position]
#pragma unroll
        for (int g = 0; g < NGRP; g++) {
            int4 w4 = *(const int4*)(s_w + g * COUT + q * 4);
            acc[0][0] = dp4a_us(xw[g][0], w4.x, acc[0][0]);
            acc[0][1] = dp4a_us(xw[g][1], w4.x, acc[0][1]);
            acc[1][0] = dp4a_us(xw[g][0], w4.y, acc[1][0]);
            acc[1][1] = dp4a_us(xw[g][1], w4.y, acc[1][1]);
            acc[2][0] = dp4a_us(xw[g][0], w4.z, acc[2][0]);
            acc[2][1] = dp4a_us(xw[g][1], w4.z, acc[2][1]);
            acc[3][0] = dp4a_us(xw[g][0], w4.w, acc[3][0]);
            acc[3][1] = dp4a_us(xw[g][1], w4.w, acc[3][1]);
        }
#pragma unroll
        for (int j = 0; j < 4; j++) {
            int o = q * 4 + j;
            float S  = s_S[o];
            float C0 = s_C0[o];
            float C1 = s_C1[o];
            float f0 = fmaf(S, (float)acc[j][0], fmaf(C1, sxf0, C0));
            float f1 = fmaf(S, (float)acc[j][1], fmaf(C1, sxf1, C0));
            float r0 = fminf(fmaxf(rintf(f0), 0.0f), 255.0f);
            float r1 = fminf(fmaxf(rintf(f1), 0.0f), 255.0f);
            out[out_base + o * (HW / 2)] = make_float2(r0, r1);
        }
    }
}

extern "C" void kernel_launch(void* const* d_in, const int* in_sizes, int n_in,
                              void* d_out, int out_size) {
    // metadata order:
    // 0: x_quant (int32)       1: input_scale (f32)   2: input_zero_point (i32)
    // 3: weight_int8 (i32)     4: weight_scale (f32)  5: weight_zero_point (i32)
    // 6: bias_fp32 (f32)       7: output_scale (f32)  8: output_zero_point (i32)
    (void)in_sizes; (void)n_in; (void)out_size;

    prep_kernel<<<1, 64>>>((const int*)d_in[3], (const float*)d_in[4],
                           (const int*)d_in[5], (const float*)d_in[6],
                           (const float*)d_in[1], (const float*)d_in[7],
                           (const int*)d_in[2], (const int*)d_in[8]);

    // 524288 positions / 2 per thread / 256 threads = 1024 blocks (exact)
    conv_kernel<<<1024, 256>>>((const int2*)d_in[0], (float2*)d_out);
}